// round 13
// baseline (speedup 1.0000x reference)
#include <cuda_runtime.h>
#include <cuda_bf16.h>
#include <math.h>
#include <stdint.h>

#define SPEC 512
#define OUTN 4096
#define INN  4096

// ---------------------------------------------------------------------------
// Scratch (__device__ globals; no allocation allowed)
// ---------------------------------------------------------------------------
__device__ float g_cpos[OUTN];
__device__ float g_cneg[OUTN];
__device__ float g_bpos[OUTN];
__device__ float g_bneg[OUTN];
__device__ float g_factor[OUTN];
__device__ __align__(16) __nv_bfloat16 g_Vhi[SPEC * OUTN];         // [s][o] row-major
__device__ __align__(16) __nv_bfloat16 g_Vlo[SPEC * OUTN];
__device__ __align__(16) __nv_bfloat16 g_Whi[(size_t)OUTN * INN];  // [o][i] row-major
__device__ __align__(16) __nv_bfloat16 g_Wlo[(size_t)OUTN * INN];

// ---------------------------------------------------------------------------
// PTX helpers (sm_80+ only — compute_103 virtual arch safe)
// ---------------------------------------------------------------------------
__device__ __forceinline__ uint32_t smem_u32(const void* p) {
    uint32_t a;
    asm("{ .reg .u64 t; cvta.to.shared.u64 t, %1; cvt.u32.u64 %0, t; }" : "=r"(a) : "l"(p));
    return a;
}
__device__ __forceinline__ void cp16(uint32_t dst, const void* src) {
    asm volatile("cp.async.cg.shared.global [%0], [%1], 16;" :: "r"(dst), "l"(src));
}
#define CP_COMMIT() asm volatile("cp.async.commit_group;" ::: "memory")
#define CP_WAIT1()  asm volatile("cp.async.wait_group 1;" ::: "memory")
#define CP_WAIT0()  asm volatile("cp.async.wait_group 0;" ::: "memory")

__device__ __forceinline__ void ldm_x4(uint32_t* r, uint32_t addr) {
    asm volatile("ldmatrix.sync.aligned.m8n8.x4.shared.b16 {%0,%1,%2,%3}, [%4];"
        : "=r"(r[0]), "=r"(r[1]), "=r"(r[2]), "=r"(r[3]) : "r"(addr));
}
__device__ __forceinline__ void ldm_x4_t(uint32_t* r, uint32_t addr) {
    asm volatile("ldmatrix.sync.aligned.m8n8.x4.trans.shared.b16 {%0,%1,%2,%3}, [%4];"
        : "=r"(r[0]), "=r"(r[1]), "=r"(r[2]), "=r"(r[3]) : "r"(addr));
}
__device__ __forceinline__ void mma_bf16(float* c, const uint32_t* a, const uint32_t* b) {
    asm volatile("mma.sync.aligned.m16n8k16.row.col.f32.bf16.bf16.f32 "
        "{%0,%1,%2,%3}, {%4,%5,%6,%7}, {%8,%9}, {%0,%1,%2,%3};"
        : "+f"(c[0]), "+f"(c[1]), "+f"(c[2]), "+f"(c[3])
        : "r"(a[0]), "r"(a[1]), "r"(a[2]), "r"(a[3]), "r"(b[0]), "r"(b[1]));
}

// ---------------------------------------------------------------------------
// Phase 0: per-output-neuron scalar coefficients (unchanged math)
// ---------------------------------------------------------------------------
__global__ void scalars_k(const float* __restrict__ bias,
                          const float* __restrict__ lb_in,
                          const float* __restrict__ ub_in,
                          const float* __restrict__ alpha)
{
    int o = blockIdx.x * blockDim.x + threadIdx.x;
    if (o >= OUTN) return;

    float b  = bias[o];
    float lb = lb_in[o];
    float ub = ub_in[o];
    float a  = alpha[o];
    float oma = 1.0f - a;

    float lo_d = (fabsf(lb) >= fabsf(ub)) ? 1.0f : 0.0f;

    float upc_s, loc_s, upb, lob, fac;
    if (ub <= 0.0f) {
        upc_s = 0.0f; loc_s = 0.0f; upb = 0.0f; lob = 0.0f; fac = 0.0f;
    } else if (lb >= 0.0f) {
        upc_s = 1.0f; loc_s = 1.0f; upb = b;    lob = b;    fac = 0.0f;
    } else {
        upc_s = 0.0f;
        loc_s = lo_d;
        upb   = fmaxf(b, 0.0f);
        lob   = lo_d * b;
        fac   = oma;
    }

    float lb_r = fminf(lb, 0.0f);
    float ub_r = fmaxf(ub, 0.0f);
    ub_r = fmaxf(ub_r, lb_r + 1e-8f);
    float ud  = ub_r / (ub_r - lb_r);
    float upB = -lb_r * ud;
    float ldd = (ud > 0.5f) ? 1.0f : 0.0f;

    g_cpos[o]   = oma * upc_s + ud * a;
    g_cneg[o]   = oma * loc_s + ldd * a;
    g_bpos[o]   = oma * upb + upB + ud * a * b;
    g_bneg[o]   = oma * lob + ldd * a * b;
    g_factor[o] = fac;
}

// ---------------------------------------------------------------------------
// Phase 1: V = pos*cpos + neg*cneg, split into bf16 hi/lo; fused ubias.
// ---------------------------------------------------------------------------
__global__ __launch_bounds__(256) void vbias_k(const float* __restrict__ uA,
                                               float* __restrict__ ubias)
{
    int s = blockIdx.x;
    const float* row = uA + (size_t)s * OUTN;
    __nv_bfloat16* vh = g_Vhi + (size_t)s * OUTN;
    __nv_bfloat16* vl = g_Vlo + (size_t)s * OUTN;

    float acc = 0.0f;
    for (int o = threadIdx.x; o < OUTN; o += 256) {
        float u = row[o];
        float p = fmaxf(u, 0.0f);
        float n = fminf(u, 0.0f);
        float v = p * g_cpos[o] + n * g_cneg[o];
        __nv_bfloat16 hi = __float2bfloat16(v);
        vh[o] = hi;
        vl[o] = __float2bfloat16(v - __bfloat162float(hi));
        acc += p * g_bpos[o] + n * g_bneg[o];
    }

    __shared__ float sred[256];
    sred[threadIdx.x] = acc;
    __syncthreads();
    #pragma unroll
    for (int st = 128; st > 0; st >>= 1) {
        if (threadIdx.x < st) sred[threadIdx.x] += sred[threadIdx.x + st];
        __syncthreads();
    }
    if (threadIdx.x == 0) ubias[s] = sred[0];
}

// ---------------------------------------------------------------------------
// Phase 1b: elementwise W -> bf16 hi/lo split. 32B per thread, uint4 stores.
// ---------------------------------------------------------------------------
__global__ __launch_bounds__(256) void wsplit_k(const float4* __restrict__ W4)
{
    size_t base = ((size_t)blockIdx.x * 256 + threadIdx.x) * 2;   // two float4s
    uint4 hv, lv;
    uint32_t* hp = &hv.x;
    uint32_t* lp = &lv.x;
    #pragma unroll
    for (int q = 0; q < 2; ++q) {
        float4 v = W4[base + q];
        __nv_bfloat162 hA, hB, lA, lB;
        hA.x = __float2bfloat16(v.x);
        hA.y = __float2bfloat16(v.y);
        hB.x = __float2bfloat16(v.z);
        hB.y = __float2bfloat16(v.w);
        lA.x = __float2bfloat16(v.x - __bfloat162float(hA.x));
        lA.y = __float2bfloat16(v.y - __bfloat162float(hA.y));
        lB.x = __float2bfloat16(v.z - __bfloat162float(hB.x));
        lB.y = __float2bfloat16(v.w - __bfloat162float(hB.y));
        hp[q * 2 + 0] = *reinterpret_cast<uint32_t*>(&hA);
        hp[q * 2 + 1] = *reinterpret_cast<uint32_t*>(&hB);
        lp[q * 2 + 0] = *reinterpret_cast<uint32_t*>(&lA);
        lp[q * 2 + 1] = *reinterpret_cast<uint32_t*>(&lB);
    }
    size_t oidx = (size_t)blockIdx.x * 256 + threadIdx.x;
    reinterpret_cast<uint4*>(g_Whi)[oidx] = hv;
    reinterpret_cast<uint4*>(g_Wlo)[oidx] = lv;
}

// ---------------------------------------------------------------------------
// Phase 2: HMMA GEMM  C[s,i] = sum_o V[s,o] * W[o,i]
// 3-term bf16 split via mma.sync m16n8k16, fp32 accum.
// CTA tile 128(M) x 64(N), BK=32, 3-stage cp.async, 8 warps (4Mx2N, 32x32 each),
// 2 CTAs/SM, single __syncthreads per chunk, double-buffered fragments.
// ---------------------------------------------------------------------------
#define BK       32
#define NCHUNK   (OUTN / BK)            // 128
#define A_ROW_B  80                     // 64B data + 16B pad
#define A_TILE   (128 * A_ROW_B)        // 10240 B
#define B_ROW_B  144                    // 128B data + 16B pad
#define B_TILE   (32 * B_ROW_B)         // 4608 B
#define STAGE_SM (2 * A_TILE + 2 * B_TILE)   // 29696 B
#define GEMM_SMEM (3 * STAGE_SM)             // 89088 B

__global__ __launch_bounds__(256, 2) void gemm_k(float* __restrict__ C)
{
    extern __shared__ char smem[];
    const uint32_t sbase = smem_u32(smem);

    const int tid = threadIdx.x;
    const int wid = tid >> 5;
    const int lid = tid & 31;
    const int bm = blockIdx.y * 128;
    const int bn = blockIdx.x * 64;
    const int wm = wid & 3;             // 4 warps in M (32 rows each)
    const int wn = wid >> 2;            // 2 warps in N (32 cols each)

    const __nv_bfloat16* srcAh = g_Vhi + (size_t)bm * OUTN;
    const __nv_bfloat16* srcAl = g_Vlo + (size_t)bm * OUTN;
    const __nv_bfloat16* srcBh = g_Whi + bn;
    const __nv_bfloat16* srcBl = g_Wlo + bn;

    // ldmatrix base offsets (bytes within an operand tile)
    const uint32_t aoff = (uint32_t)((wm * 32 + (lid & 15)) * A_ROW_B + (lid >> 4) * 16);
    const uint32_t boff = (uint32_t)((lid & 15) * B_ROW_B + wn * 64 + (lid >> 4) * 16);

    auto load_chunk = [&](int chunk, int st) {
        uint32_t stage = sbase + st * STAGE_SM;
        int k0 = chunk * BK;
        #pragma unroll
        for (int i = 0; i < 2; ++i) {   // A hi/lo: 128 rows x 4 x 16B
            int u = tid + i * 256;      // 0..511
            int row = u >> 2, c16 = u & 3;
            uint32_t d = stage + (uint32_t)(row * A_ROW_B + c16 * 16);
            cp16(d,          srcAh + (size_t)row * OUTN + k0 + c16 * 8);
            cp16(d + A_TILE, srcAl + (size_t)row * OUTN + k0 + c16 * 8);
        }
        {   // B hi/lo: 32 rows x 8 x 16B
            int row = tid >> 3, u = tid & 7;
            uint32_t d = stage + 2 * A_TILE + (uint32_t)(row * B_ROW_B + u * 16);
            cp16(d,          srcBh + (size_t)(k0 + row) * INN + u * 8);
            cp16(d + B_TILE, srcBl + (size_t)(k0 + row) * INN + u * 8);
        }
        CP_COMMIT();
    };

    float acc[2][4][4] = {};
    uint32_t ah[2][2][4], al[2][2][4], bh[2][2][4], bl[2][2][4];

    auto ld_frags = [&](int buf, uint32_t stg, int ks) {
        uint32_t aHi = stg, aLo = stg + A_TILE;
        uint32_t bHi = stg + 2 * A_TILE, bLo = bHi + B_TILE;
        #pragma unroll
        for (int mt = 0; mt < 2; ++mt) {
            uint32_t a = (uint32_t)(mt * 16 * A_ROW_B + ks * 32) + aoff;
            ldm_x4(ah[buf][mt], aHi + a);
            ldm_x4(al[buf][mt], aLo + a);
        }
        #pragma unroll
        for (int p = 0; p < 2; ++p) {
            uint32_t b = (uint32_t)(ks * 16 * B_ROW_B + p * 32) + boff;
            ldm_x4_t(bh[buf][p], bHi + b);
            ldm_x4_t(bl[buf][p], bLo + b);
        }
    };

    load_chunk(0, 0);
    load_chunk(1, 1);

    for (int c = 0; c < NCHUNK; ++c) {
        if (c + 1 < NCHUNK) CP_WAIT1(); else CP_WAIT0();
        __syncthreads();
        // overwrites stage of chunk c-1; every warp finished it before this sync
        if (c + 2 < NCHUNK) load_chunk(c + 2, (c + 2) % 3);

        uint32_t stg = sbase + (c % 3) * STAGE_SM;
        ld_frags(0, stg, 0);
        #pragma unroll
        for (int ks = 0; ks < 2; ++ks) {
            if (ks == 0) ld_frags(1, stg, 1);
            #pragma unroll
            for (int mt = 0; mt < 2; ++mt)
                #pragma unroll
                for (int nt = 0; nt < 4; ++nt) {
                    const uint32_t* BH = &bh[ks][nt >> 1][(nt & 1) * 2];
                    const uint32_t* BL = &bl[ks][nt >> 1][(nt & 1) * 2];
                    mma_bf16(acc[mt][nt], ah[ks][mt], BH);
                    mma_bf16(acc[mt][nt], ah[ks][mt], BL);
                    mma_bf16(acc[mt][nt], al[ks][mt], BH);
                }
        }
    }

    // epilogue: fragment -> gmem (float2 stores)
    const int r0 = bm + wm * 32 + (lid >> 2);
    const int c0 = bn + wn * 32 + (lid & 3) * 2;
    #pragma unroll
    for (int mt = 0; mt < 2; ++mt) {
        #pragma unroll
        for (int nt = 0; nt < 4; ++nt) {
            int row = r0 + mt * 16;
            int col = c0 + nt * 8;
            *reinterpret_cast<float2*>(&C[(size_t)row * INN + col]) =
                make_float2(acc[mt][nt][0], acc[mt][nt][1]);
            *reinterpret_cast<float2*>(&C[(size_t)(row + 8) * INN + col]) =
                make_float2(acc[mt][nt][2], acc[mt][nt][3]);
        }
    }
}

// ---------------------------------------------------------------------------
// Phase 3: simplex residual for unstable neurons with alpha != 1 (zero here).
// ---------------------------------------------------------------------------
__global__ void residual_k(const float* __restrict__ uA,
                           const float* __restrict__ W,
                           const float* __restrict__ bias,
                           float* __restrict__ out)
{
    for (int o = blockIdx.x; o < OUTN; o += gridDim.x) {
        float f = g_factor[o];
        if (f == 0.0f) continue;

        float b  = bias[o];
        float rb = fmaxf(b, 0.0f);
        for (int s = 0; s < SPEC; s++) {
            float p = fmaxf(uA[(size_t)s * OUTN + o], 0.0f);
            float coef = p * f;
            if (coef == 0.0f) continue;
            for (int i = threadIdx.x; i < INN; i += blockDim.x) {
                float sc = fmaxf(W[(size_t)o * INN + i] + b, 0.0f) - rb;
                atomicAdd(&out[(size_t)s * INN + i], coef * sc);
            }
        }
    }
}

// ---------------------------------------------------------------------------
// Launch
// ---------------------------------------------------------------------------
extern "C" void kernel_launch(void* const* d_in, const int* in_sizes, int n_in,
                              void* d_out, int out_size)
{
    const float* uA    = (const float*)d_in[0];
    const float* W     = (const float*)d_in[1];
    const float* bias  = (const float*)d_in[2];
    const float* lb    = (const float*)d_in[3];
    const float* ub    = (const float*)d_in[4];
    const float* alpha = (const float*)d_in[5];

    float* out_uA   = (float*)d_out;
    float* out_bias = out_uA + (size_t)SPEC * INN;

    static bool attr_done = false;
    if (!attr_done) {
        cudaFuncSetAttribute(gemm_k, cudaFuncAttributeMaxDynamicSharedMemorySize, GEMM_SMEM);
        attr_done = true;
    }

    scalars_k<<<OUTN / 256, 256>>>(bias, lb, ub, alpha);
    wsplit_k<<<(OUTN * (INN / 8)) / 256, 256>>>((const float4*)W);
    vbias_k<<<SPEC, 256>>>(uA, out_bias);
    gemm_k<<<dim3(INN / 64, SPEC / 128), 256, GEMM_SMEM>>>(out_uA);
    residual_k<<<64, 128>>>(uA, W, bias, out_uA);
}

// round 14
// speedup vs baseline: 1.3745x; 1.3745x over previous
#include <cuda_runtime.h>
#include <cuda_fp16.h>
#include <math.h>
#include <stdint.h>

#define SPEC 512
#define OUTN 4096
#define INN  4096

// ---------------------------------------------------------------------------
// Scratch (__device__ globals; no allocation allowed)
// ---------------------------------------------------------------------------
__device__ float g_cpos[OUTN];
__device__ float g_cneg[OUTN];
__device__ float g_bpos[OUTN];
__device__ float g_bneg[OUTN];
__device__ float g_factor[OUTN];
__device__ __align__(16) __half g_Vhi[SPEC * OUTN];        // [s][o] fp16 hi part of V
__device__ __align__(16) __half g_Vlo[SPEC * OUTN];        // [s][o] fp16 lo part of V
__device__ __align__(16) __half g_Wh[(size_t)OUTN * INN];  // [o][i] fp16 W

// ---------------------------------------------------------------------------
// PTX helpers (sm_80+ only — compute_103 virtual arch safe)
// ---------------------------------------------------------------------------
__device__ __forceinline__ uint32_t smem_u32(const void* p) {
    uint32_t a;
    asm("{ .reg .u64 t; cvta.to.shared.u64 t, %1; cvt.u32.u64 %0, t; }" : "=r"(a) : "l"(p));
    return a;
}
__device__ __forceinline__ void cp16(uint32_t dst, const void* src) {
    asm volatile("cp.async.cg.shared.global [%0], [%1], 16;" :: "r"(dst), "l"(src));
}
#define CP_COMMIT() asm volatile("cp.async.commit_group;" ::: "memory")
#define CP_WAIT1()  asm volatile("cp.async.wait_group 1;" ::: "memory")
#define CP_WAIT0()  asm volatile("cp.async.wait_group 0;" ::: "memory")

__device__ __forceinline__ void ldm_x4(uint32_t* r, uint32_t addr) {
    asm volatile("ldmatrix.sync.aligned.m8n8.x4.shared.b16 {%0,%1,%2,%3}, [%4];"
        : "=r"(r[0]), "=r"(r[1]), "=r"(r[2]), "=r"(r[3]) : "r"(addr));
}
__device__ __forceinline__ void ldm_x4_t(uint32_t* r, uint32_t addr) {
    asm volatile("ldmatrix.sync.aligned.m8n8.x4.trans.shared.b16 {%0,%1,%2,%3}, [%4];"
        : "=r"(r[0]), "=r"(r[1]), "=r"(r[2]), "=r"(r[3]) : "r"(addr));
}
__device__ __forceinline__ void mma_fp16(float* c, const uint32_t* a, const uint32_t* b) {
    asm volatile("mma.sync.aligned.m16n8k16.row.col.f32.f16.f16.f32 "
        "{%0,%1,%2,%3}, {%4,%5,%6,%7}, {%8,%9}, {%0,%1,%2,%3};"
        : "+f"(c[0]), "+f"(c[1]), "+f"(c[2]), "+f"(c[3])
        : "r"(a[0]), "r"(a[1]), "r"(a[2]), "r"(a[3]), "r"(b[0]), "r"(b[1]));
}

// ---------------------------------------------------------------------------
// Phase 0: per-output-neuron scalar coefficients (unchanged math)
// ---------------------------------------------------------------------------
__global__ void scalars_k(const float* __restrict__ bias,
                          const float* __restrict__ lb_in,
                          const float* __restrict__ ub_in,
                          const float* __restrict__ alpha)
{
    int o = blockIdx.x * blockDim.x + threadIdx.x;
    if (o >= OUTN) return;

    float b  = bias[o];
    float lb = lb_in[o];
    float ub = ub_in[o];
    float a  = alpha[o];
    float oma = 1.0f - a;

    float lo_d = (fabsf(lb) >= fabsf(ub)) ? 1.0f : 0.0f;

    float upc_s, loc_s, upb, lob, fac;
    if (ub <= 0.0f) {
        upc_s = 0.0f; loc_s = 0.0f; upb = 0.0f; lob = 0.0f; fac = 0.0f;
    } else if (lb >= 0.0f) {
        upc_s = 1.0f; loc_s = 1.0f; upb = b;    lob = b;    fac = 0.0f;
    } else {
        upc_s = 0.0f;
        loc_s = lo_d;
        upb   = fmaxf(b, 0.0f);
        lob   = lo_d * b;
        fac   = oma;
    }

    float lb_r = fminf(lb, 0.0f);
    float ub_r = fmaxf(ub, 0.0f);
    ub_r = fmaxf(ub_r, lb_r + 1e-8f);
    float ud  = ub_r / (ub_r - lb_r);
    float upB = -lb_r * ud;
    float ldd = (ud > 0.5f) ? 1.0f : 0.0f;

    g_cpos[o]   = oma * upc_s + ud * a;
    g_cneg[o]   = oma * loc_s + ldd * a;
    g_bpos[o]   = oma * upb + upB + ud * a * b;
    g_bneg[o]   = oma * lob + ldd * a * b;
    g_factor[o] = fac;
}

// ---------------------------------------------------------------------------
// Phase 1: V = pos*cpos + neg*cneg, split into fp16 hi/lo; fused ubias.
// ---------------------------------------------------------------------------
__global__ __launch_bounds__(256) void vbias_k(const float* __restrict__ uA,
                                               float* __restrict__ ubias)
{
    int s = blockIdx.x;
    const float* row = uA + (size_t)s * OUTN;
    __half* vh = g_Vhi + (size_t)s * OUTN;
    __half* vl = g_Vlo + (size_t)s * OUTN;

    float acc = 0.0f;
    for (int o = threadIdx.x; o < OUTN; o += 256) {
        float u = row[o];
        float p = fmaxf(u, 0.0f);
        float n = fminf(u, 0.0f);
        float v = p * g_cpos[o] + n * g_cneg[o];
        __half hi = __float2half_rn(v);
        vh[o] = hi;
        vl[o] = __float2half_rn(v - __half2float(hi));
        acc += p * g_bpos[o] + n * g_bneg[o];
    }

    __shared__ float sred[256];
    sred[threadIdx.x] = acc;
    __syncthreads();
    #pragma unroll
    for (int st = 128; st > 0; st >>= 1) {
        if (threadIdx.x < st) sred[threadIdx.x] += sred[threadIdx.x + st];
        __syncthreads();
    }
    if (threadIdx.x == 0) ubias[s] = sred[0];
}

// ---------------------------------------------------------------------------
// Phase 1b: elementwise W fp32 -> fp16 (single, no split). 8 floats/thread.
// ---------------------------------------------------------------------------
__global__ __launch_bounds__(256) void whalf_k(const float4* __restrict__ W4)
{
    size_t base = ((size_t)blockIdx.x * 256 + threadIdx.x) * 2;   // two float4s
    uint4 hv;
    uint32_t* hp = &hv.x;
    #pragma unroll
    for (int q = 0; q < 2; ++q) {
        float4 v = W4[base + q];
        __half2 a = __floats2half2_rn(v.x, v.y);
        __half2 b = __floats2half2_rn(v.z, v.w);
        hp[q * 2 + 0] = *reinterpret_cast<uint32_t*>(&a);
        hp[q * 2 + 1] = *reinterpret_cast<uint32_t*>(&b);
    }
    reinterpret_cast<uint4*>(g_Wh)[(size_t)blockIdx.x * 256 + threadIdx.x] = hv;
}

// ---------------------------------------------------------------------------
// Phase 2: HMMA GEMM  C[s,i] = sum_o V[s,o] * W[o,i]
// Asymmetric 2-term fp16 split: Vhi*W + Vlo*W, fp32 accum.
// 128x128 CTA tile, BK=32, 3-stage cp.async, 16 warps (4Mx4N, 32x32 each),
// single __syncthreads per chunk, double-buffered fragments.
// ---------------------------------------------------------------------------
#define BK       32
#define NCHUNK   (OUTN / BK)            // 128
#define A_ROW_B  80                     // 64B data + 16B pad
#define A_TILE   (128 * A_ROW_B)        // 10240 B
#define B_ROW_B  272                    // 256B data + 16B pad
#define B_TILE   (32 * B_ROW_B)         // 8704 B
#define STAGE_SM (2 * A_TILE + B_TILE)  // 29184 B (Ahi, Alo, W)
#define GEMM_SMEM (3 * STAGE_SM)        // 87552 B

__global__ __launch_bounds__(512, 1) void gemm_k(float* __restrict__ C)
{
    extern __shared__ char smem[];
    const uint32_t sbase = smem_u32(smem);

    const int tid = threadIdx.x;
    const int wid = tid >> 5;
    const int lid = tid & 31;
    const int bm = blockIdx.y * 128;
    const int bn = blockIdx.x * 128;
    const int wm = wid & 3;             // 4 warps in M (32 rows each)
    const int wn = wid >> 2;            // 4 warps in N (32 cols each)

    const __half* srcAh = g_Vhi + (size_t)bm * OUTN;
    const __half* srcAl = g_Vlo + (size_t)bm * OUTN;
    const __half* srcB  = g_Wh + bn;

    // ldmatrix base offsets (bytes within an operand tile)
    const uint32_t aoff = (uint32_t)((wm * 32 + (lid & 15)) * A_ROW_B + (lid >> 4) * 16);
    const uint32_t boff = (uint32_t)((lid & 15) * B_ROW_B + wn * 64 + (lid >> 4) * 16);

    auto load_chunk = [&](int chunk, int st) {
        uint32_t stage = sbase + st * STAGE_SM;
        int k0 = chunk * BK;
        {   // A hi/lo: 128 rows x 4 x 16B each; 512 threads -> 1 cp16 per operand
            int row = tid >> 2, c16 = tid & 3;
            uint32_t d = stage + (uint32_t)(row * A_ROW_B + c16 * 16);
            cp16(d,          srcAh + (size_t)row * OUTN + k0 + c16 * 8);
            cp16(d + A_TILE, srcAl + (size_t)row * OUTN + k0 + c16 * 8);
        }
        if (tid < 256) {   // B: 32 rows x 16 x 16B = 512 cp16; 2 per thread
            int row = tid >> 3, u = tid & 7;
            uint32_t d = stage + 2 * A_TILE + (uint32_t)(row * B_ROW_B);
            const __half* s = srcB + (size_t)(k0 + row) * INN;
            cp16(d + (uint32_t)(u * 16),         s + u * 8);
            cp16(d + (uint32_t)((u + 8) * 16),   s + (u + 8) * 8);
        }
        CP_COMMIT();
    };

    float acc[2][4][4] = {};
    uint32_t ah[2][2][4], al[2][2][4], bf[2][2][4];

    auto ld_frags = [&](int buf, uint32_t stg, int ks) {
        uint32_t aHi = stg, aLo = stg + A_TILE;
        uint32_t bB  = stg + 2 * A_TILE;
        #pragma unroll
        for (int mt = 0; mt < 2; ++mt) {
            uint32_t a = (uint32_t)(mt * 16 * A_ROW_B + ks * 32) + aoff;
            ldm_x4(ah[buf][mt], aHi + a);
            ldm_x4(al[buf][mt], aLo + a);
        }
        #pragma unroll
        for (int p = 0; p < 2; ++p) {
            uint32_t b = (uint32_t)(ks * 16 * B_ROW_B + p * 32) + boff;
            ldm_x4_t(bf[buf][p], bB + b);
        }
    };

    load_chunk(0, 0);
    load_chunk(1, 1);

    for (int c = 0; c < NCHUNK; ++c) {
        if (c + 1 < NCHUNK) CP_WAIT1(); else CP_WAIT0();
        __syncthreads();
        // stage of chunk c-1 is free: every warp passed the previous sync
        if (c + 2 < NCHUNK) load_chunk(c + 2, (c + 2) % 3);

        uint32_t stg = sbase + (c % 3) * STAGE_SM;
        ld_frags(0, stg, 0);
        #pragma unroll
        for (int ks = 0; ks < 2; ++ks) {
            if (ks == 0) ld_frags(1, stg, 1);
            #pragma unroll
            for (int mt = 0; mt < 2; ++mt)
                #pragma unroll
                for (int nt = 0; nt < 4; ++nt) {
                    const uint32_t* B = &bf[ks][nt >> 1][(nt & 1) * 2];
                    mma_fp16(acc[mt][nt], ah[ks][mt], B);
                    mma_fp16(acc[mt][nt], al[ks][mt], B);
                }
        }
    }

    // epilogue: fragment -> gmem (float2 stores)
    const int r0 = bm + wm * 32 + (lid >> 2);
    const int c0 = bn + wn * 32 + (lid & 3) * 2;
    #pragma unroll
    for (int mt = 0; mt < 2; ++mt) {
        #pragma unroll
        for (int nt = 0; nt < 4; ++nt) {
            int row = r0 + mt * 16;
            int col = c0 + nt * 8;
            *reinterpret_cast<float2*>(&C[(size_t)row * INN + col]) =
                make_float2(acc[mt][nt][0], acc[mt][nt][1]);
            *reinterpret_cast<float2*>(&C[(size_t)(row + 8) * INN + col]) =
                make_float2(acc[mt][nt][2], acc[mt][nt][3]);
        }
    }
}

// ---------------------------------------------------------------------------
// Phase 3: simplex residual for unstable neurons with alpha != 1 (zero here).
// ---------------------------------------------------------------------------
__global__ void residual_k(const float* __restrict__ uA,
                           const float* __restrict__ W,
                           const float* __restrict__ bias,
                           float* __restrict__ out)
{
    for (int o = blockIdx.x; o < OUTN; o += gridDim.x) {
        float f = g_factor[o];
        if (f == 0.0f) continue;

        float b  = bias[o];
        float rb = fmaxf(b, 0.0f);
        for (int s = 0; s < SPEC; s++) {
            float p = fmaxf(uA[(size_t)s * OUTN + o], 0.0f);
            float coef = p * f;
            if (coef == 0.0f) continue;
            for (int i = threadIdx.x; i < INN; i += blockDim.x) {
                float sc = fmaxf(W[(size_t)o * INN + i] + b, 0.0f) - rb;
                atomicAdd(&out[(size_t)s * INN + i], coef * sc);
            }
        }
    }
}

// ---------------------------------------------------------------------------
// Launch
// ---------------------------------------------------------------------------
extern "C" void kernel_launch(void* const* d_in, const int* in_sizes, int n_in,
                              void* d_out, int out_size)
{
    const float* uA    = (const float*)d_in[0];
    const float* W     = (const float*)d_in[1];
    const float* bias  = (const float*)d_in[2];
    const float* lb    = (const float*)d_in[3];
    const float* ub    = (const float*)d_in[4];
    const float* alpha = (const float*)d_in[5];

    float* out_uA   = (float*)d_out;
    float* out_bias = out_uA + (size_t)SPEC * INN;

    static bool attr_done = false;
    if (!attr_done) {
        cudaFuncSetAttribute(gemm_k, cudaFuncAttributeMaxDynamicSharedMemorySize, GEMM_SMEM);
        attr_done = true;
    }

    scalars_k<<<OUTN / 256, 256>>>(bias, lb, ub, alpha);
    whalf_k<<<(OUTN * (INN / 8)) / 256, 256>>>((const float4*)W);
    vbias_k<<<SPEC, 256>>>(uA, out_bias);
    gemm_k<<<dim3(INN / 128, SPEC / 128), 512, GEMM_SMEM>>>(out_uA);
    residual_k<<<64, 128>>>(uA, W, bias, out_uA);
}

// round 16
// speedup vs baseline: 1.9274x; 1.4023x over previous
#include <cuda_runtime.h>
#include <cuda_fp16.h>
#include <math.h>
#include <stdint.h>

#define SPEC 512
#define OUTN 4096
#define INN  4096

// ---------------------------------------------------------------------------
// Scratch (__device__ globals; no allocation allowed)
// ---------------------------------------------------------------------------
__device__ float g_cpos[OUTN];
__device__ float g_cneg[OUTN];
__device__ float g_bpos[OUTN];
__device__ float g_bneg[OUTN];
__device__ float g_factor[OUTN];
__device__ __align__(16) __half g_Vh[SPEC * OUTN];         // [s][o] fp16 V
__device__ __align__(16) __half g_Wh[(size_t)OUTN * INN];  // [o][i] fp16 W

// ---------------------------------------------------------------------------
// PTX helpers (sm_80+ only — compute_103 virtual arch safe)
// ---------------------------------------------------------------------------
__device__ __forceinline__ uint32_t smem_u32(const void* p) {
    uint32_t a;
    asm("{ .reg .u64 t; cvta.to.shared.u64 t, %1; cvt.u32.u64 %0, t; }" : "=r"(a) : "l"(p));
    return a;
}
__device__ __forceinline__ void cp16(uint32_t dst, const void* src) {
    asm volatile("cp.async.cg.shared.global [%0], [%1], 16;" :: "r"(dst), "l"(src));
}
#define CP_COMMIT() asm volatile("cp.async.commit_group;" ::: "memory")
#define CP_WAIT1()  asm volatile("cp.async.wait_group 1;" ::: "memory")
#define CP_WAIT0()  asm volatile("cp.async.wait_group 0;" ::: "memory")

__device__ __forceinline__ void ldm_x4(uint32_t* r, uint32_t addr) {
    asm volatile("ldmatrix.sync.aligned.m8n8.x4.shared.b16 {%0,%1,%2,%3}, [%4];"
        : "=r"(r[0]), "=r"(r[1]), "=r"(r[2]), "=r"(r[3]) : "r"(addr));
}
__device__ __forceinline__ void ldm_x4_t(uint32_t* r, uint32_t addr) {
    asm volatile("ldmatrix.sync.aligned.m8n8.x4.trans.shared.b16 {%0,%1,%2,%3}, [%4];"
        : "=r"(r[0]), "=r"(r[1]), "=r"(r[2]), "=r"(r[3]) : "r"(addr));
}
__device__ __forceinline__ void mma_fp16(float* c, const uint32_t* a, const uint32_t* b) {
    asm volatile("mma.sync.aligned.m16n8k16.row.col.f32.f16.f16.f32 "
        "{%0,%1,%2,%3}, {%4,%5,%6,%7}, {%8,%9}, {%0,%1,%2,%3};"
        : "+f"(c[0]), "+f"(c[1]), "+f"(c[2]), "+f"(c[3])
        : "r"(a[0]), "r"(a[1]), "r"(a[2]), "r"(a[3]), "r"(b[0]), "r"(b[1]));
}

// ---------------------------------------------------------------------------
// Phase 0: per-output-neuron scalar coefficients (unchanged math)
// ---------------------------------------------------------------------------
__global__ void scalars_k(const float* __restrict__ bias,
                          const float* __restrict__ lb_in,
                          const float* __restrict__ ub_in,
                          const float* __restrict__ alpha)
{
    int o = blockIdx.x * blockDim.x + threadIdx.x;
    if (o >= OUTN) return;

    float b  = bias[o];
    float lb = lb_in[o];
    float ub = ub_in[o];
    float a  = alpha[o];
    float oma = 1.0f - a;

    float lo_d = (fabsf(lb) >= fabsf(ub)) ? 1.0f : 0.0f;

    float upc_s, loc_s, upb, lob, fac;
    if (ub <= 0.0f) {
        upc_s = 0.0f; loc_s = 0.0f; upb = 0.0f; lob = 0.0f; fac = 0.0f;
    } else if (lb >= 0.0f) {
        upc_s = 1.0f; loc_s = 1.0f; upb = b;    lob = b;    fac = 0.0f;
    } else {
        upc_s = 0.0f;
        loc_s = lo_d;
        upb   = fmaxf(b, 0.0f);
        lob   = lo_d * b;
        fac   = oma;
    }

    float lb_r = fminf(lb, 0.0f);
    float ub_r = fmaxf(ub, 0.0f);
    ub_r = fmaxf(ub_r, lb_r + 1e-8f);
    float ud  = ub_r / (ub_r - lb_r);
    float upB = -lb_r * ud;
    float ldd = (ud > 0.5f) ? 1.0f : 0.0f;

    g_cpos[o]   = oma * upc_s + ud * a;
    g_cneg[o]   = oma * loc_s + ldd * a;
    g_bpos[o]   = oma * upb + upB + ud * a * b;
    g_bneg[o]   = oma * lob + ldd * a * b;
    g_factor[o] = fac;
}

// ---------------------------------------------------------------------------
// Phase 1: V = pos*cpos + neg*cneg -> fp16; fused ubias reduction.
// ---------------------------------------------------------------------------
__global__ __launch_bounds__(256) void vbias_k(const float* __restrict__ uA,
                                               float* __restrict__ ubias)
{
    int s = blockIdx.x;
    const float* row = uA + (size_t)s * OUTN;
    __half* vh = g_Vh + (size_t)s * OUTN;

    float acc = 0.0f;
    for (int o = threadIdx.x; o < OUTN; o += 256) {
        float u = row[o];
        float p = fmaxf(u, 0.0f);
        float n = fminf(u, 0.0f);
        float v = p * g_cpos[o] + n * g_cneg[o];
        vh[o] = __float2half_rn(v);
        acc += p * g_bpos[o] + n * g_bneg[o];
    }

    __shared__ float sred[256];
    sred[threadIdx.x] = acc;
    __syncthreads();
    #pragma unroll
    for (int st = 128; st > 0; st >>= 1) {
        if (threadIdx.x < st) sred[threadIdx.x] += sred[threadIdx.x + st];
        __syncthreads();
    }
    if (threadIdx.x == 0) ubias[s] = sred[0];
}

// ---------------------------------------------------------------------------
// Phase 1b: elementwise W fp32 -> fp16. 8 floats/thread, uint4 stores.
// ---------------------------------------------------------------------------
__global__ __launch_bounds__(256) void whalf_k(const float4* __restrict__ W4)
{
    size_t base = ((size_t)blockIdx.x * 256 + threadIdx.x) * 2;   // two float4s
    uint4 hv;
    uint32_t* hp = &hv.x;
    #pragma unroll
    for (int q = 0; q < 2; ++q) {
        float4 v = W4[base + q];
        __half2 a = __floats2half2_rn(v.x, v.y);
        __half2 b = __floats2half2_rn(v.z, v.w);
        hp[q * 2 + 0] = *reinterpret_cast<uint32_t*>(&a);
        hp[q * 2 + 1] = *reinterpret_cast<uint32_t*>(&b);
    }
    reinterpret_cast<uint4*>(g_Wh)[(size_t)blockIdx.x * 256 + threadIdx.x] = hv;
}

// ---------------------------------------------------------------------------
// Phase 2: HMMA GEMM  C[s,i] = sum_o V[s,o] * W[o,i]
// Single-term fp16 (fp32 accum). 128x128 CTA tile, BK=64, 3-stage cp.async,
// 16 warps (4Mx4N, 32x32 each), one __syncthreads per chunk, double-buffered
// ldmatrix fragments across the 4 ks-steps.
// ---------------------------------------------------------------------------
#define BK       64
#define NCHUNK   (OUTN / BK)            // 64
#define A_ROW_B  144                    // 128B data + 16B pad
#define A_TILE   (128 * A_ROW_B)        // 18432 B
#define B_ROW_B  272                    // 256B data + 16B pad
#define B_TILE   (64 * B_ROW_B)         // 17408 B
#define STAGE_SM (A_TILE + B_TILE)      // 35840 B
#define GEMM_SMEM (3 * STAGE_SM)        // 107520 B

__global__ __launch_bounds__(512, 1) void gemm_k(float* __restrict__ C)
{
    extern __shared__ char smem[];
    const uint32_t sbase = smem_u32(smem);

    const int tid = threadIdx.x;
    const int wid = tid >> 5;
    const int lid = tid & 31;
    const int bm = blockIdx.y * 128;
    const int bn = blockIdx.x * 128;
    const int wm = wid & 3;             // 4 warps in M (32 rows each)
    const int wn = wid >> 2;            // 4 warps in N (32 cols each)

    const __half* srcA = g_Vh + (size_t)bm * OUTN;
    const __half* srcB = g_Wh + bn;

    // ldmatrix base offsets (bytes within an operand tile)
    const uint32_t aoff = (uint32_t)((wm * 32 + (lid & 15)) * A_ROW_B + (lid >> 4) * 16);
    const uint32_t boff = (uint32_t)((lid & 15) * B_ROW_B + wn * 64 + (lid >> 4) * 16);

    auto load_chunk = [&](int chunk, int st) {
        uint32_t stage = sbase + st * STAGE_SM;
        int k0 = chunk * BK;
        #pragma unroll
        for (int i = 0; i < 2; ++i) {   // A: 128 rows x 8 x 16B = 1024 cp16
            int u = tid + i * 512;
            int row = u >> 3, c16 = u & 7;
            cp16(stage + (uint32_t)(row * A_ROW_B + c16 * 16),
                 srcA + (size_t)row * OUTN + k0 + c16 * 8);
        }
        #pragma unroll
        for (int i = 0; i < 2; ++i) {   // B: 64 rows x 16 x 16B = 1024 cp16
            int u = tid + i * 512;
            int row = u >> 4, c16 = u & 15;
            cp16(stage + A_TILE + (uint32_t)(row * B_ROW_B + c16 * 16),
                 srcB + (size_t)(k0 + row) * INN + c16 * 8);
        }
        CP_COMMIT();
    };

    float acc[2][4][4] = {};
    uint32_t ah[2][2][4], bf[2][2][4];

    auto ld_frags = [&](int buf, uint32_t stg, int ks) {
        #pragma unroll
        for (int mt = 0; mt < 2; ++mt)
            ldm_x4(ah[buf][mt], stg + (uint32_t)(mt * 16 * A_ROW_B + ks * 32) + aoff);
        #pragma unroll
        for (int p = 0; p < 2; ++p)
            ldm_x4_t(bf[buf][p], stg + A_TILE + (uint32_t)(ks * 16 * B_ROW_B + p * 32) + boff);
    };

    load_chunk(0, 0);
    load_chunk(1, 1);

    for (int c = 0; c < NCHUNK; ++c) {
        if (c + 1 < NCHUNK) CP_WAIT1(); else CP_WAIT0();
        __syncthreads();
        // stage of chunk c-1 is free: every warp passed the previous sync
        if (c + 2 < NCHUNK) load_chunk(c + 2, (c + 2) % 3);

        uint32_t stg = sbase + (c % 3) * STAGE_SM;
        ld_frags(0, stg, 0);
        #pragma unroll
        for (int ks = 0; ks < 4; ++ks) {
            if (ks < 3) ld_frags((ks + 1) & 1, stg, ks + 1);
            int buf = ks & 1;
            #pragma unroll
            for (int mt = 0; mt < 2; ++mt)
                #pragma unroll
                for (int nt = 0; nt < 4; ++nt)
                    mma_fp16(acc[mt][nt], ah[buf][mt], &bf[buf][nt >> 1][(nt & 1) * 2]);
        }
    }

    // epilogue: fragment -> gmem (float2 stores)
    const int r0 = bm + wm * 32 + (lid >> 2);
    const int c0 = bn + wn * 32 + (lid & 3) * 2;
    #pragma unroll
    for (int mt = 0; mt < 2; ++mt) {
        #pragma unroll
        for (int nt = 0; nt < 4; ++nt) {
            int row = r0 + mt * 16;
            int col = c0 + nt * 8;
            *reinterpret_cast<float2*>(&C[(size_t)row * INN + col]) =
                make_float2(acc[mt][nt][0], acc[mt][nt][1]);
            *reinterpret_cast<float2*>(&C[(size_t)(row + 8) * INN + col]) =
                make_float2(acc[mt][nt][2], acc[mt][nt][3]);
        }
    }
}

// ---------------------------------------------------------------------------
// Phase 3: simplex residual for unstable neurons with alpha != 1 (zero here).
// ---------------------------------------------------------------------------
__global__ void residual_k(const float* __restrict__ uA,
                           const float* __restrict__ W,
                           const float* __restrict__ bias,
                           float* __restrict__ out)
{
    for (int o = blockIdx.x; o < OUTN; o += gridDim.x) {
        float f = g_factor[o];
        if (f == 0.0f) continue;

        float b  = bias[o];
        float rb = fmaxf(b, 0.0f);
        for (int s = 0; s < SPEC; s++) {
            float p = fmaxf(uA[(size_t)s * OUTN + o], 0.0f);
            float coef = p * f;
            if (coef == 0.0f) continue;
            for (int i = threadIdx.x; i < INN; i += blockDim.x) {
                float sc = fmaxf(W[(size_t)o * INN + i] + b, 0.0f) - rb;
                atomicAdd(&out[(size_t)s * INN + i], coef * sc);
            }
        }
    }
}

// ---------------------------------------------------------------------------
// Launch
// ---------------------------------------------------------------------------
extern "C" void kernel_launch(void* const* d_in, const int* in_sizes, int n_in,
                              void* d_out, int out_size)
{
    const float* uA    = (const float*)d_in[0];
    const float* W     = (const float*)d_in[1];
    const float* bias  = (const float*)d_in[2];
    const float* lb    = (const float*)d_in[3];
    const float* ub    = (const float*)d_in[4];
    const float* alpha = (const float*)d_in[5];

    float* out_uA   = (float*)d_out;
    float* out_bias = out_uA + (size_t)SPEC * INN;

    static bool attr_done = false;
    if (!attr_done) {
        cudaFuncSetAttribute(gemm_k, cudaFuncAttributeMaxDynamicSharedMemorySize, GEMM_SMEM);
        attr_done = true;
    }

    scalars_k<<<OUTN / 256, 256>>>(bias, lb, ub, alpha);
    whalf_k<<<(OUTN * (INN / 8)) / 256, 256>>>((const float4*)W);
    vbias_k<<<SPEC, 256>>>(uA, out_bias);
    gemm_k<<<dim3(INN / 128, SPEC / 128), 512, GEMM_SMEM>>>(out_uA);
    residual_k<<<64, 128>>>(uA, W, bias, out_uA);
}